// round 1
// baseline (speedup 1.0000x reference)
#include <cuda_runtime.h>
#include <cuda_bf16.h>

// relu(sum(relu(x))) over N = 2^25 fp32. HBM-bound streaming reduction.
// Deterministic two-pass: blocks -> partials -> final single-block reduce.

#define NBLOCKS 1024
#define NTHREADS 256

__device__ float g_partials[NBLOCKS];

__global__ __launch_bounds__(NTHREADS) void kan_partial_kernel(
    const float* __restrict__ x, int n_vec4)
{
    const float4* __restrict__ xv = reinterpret_cast<const float4*>(x);
    int tid = blockIdx.x * blockDim.x + threadIdx.x;
    int stride = gridDim.x * blockDim.x;

    float acc = 0.0f;
    // Grid-stride over float4; relu then accumulate.
    for (int i = tid; i < n_vec4; i += stride) {
        float4 v = xv[i];
        acc += fmaxf(v.x, 0.0f);
        acc += fmaxf(v.y, 0.0f);
        acc += fmaxf(v.z, 0.0f);
        acc += fmaxf(v.w, 0.0f);
    }

    // Warp reduce
    #pragma unroll
    for (int off = 16; off > 0; off >>= 1)
        acc += __shfl_xor_sync(0xFFFFFFFFu, acc, off);

    // Block reduce via smem
    __shared__ float warp_sums[NTHREADS / 32];
    int lane = threadIdx.x & 31;
    int wid = threadIdx.x >> 5;
    if (lane == 0) warp_sums[wid] = acc;
    __syncthreads();

    if (wid == 0) {
        float s = (lane < NTHREADS / 32) ? warp_sums[lane] : 0.0f;
        #pragma unroll
        for (int off = 16; off > 0; off >>= 1)
            s += __shfl_xor_sync(0xFFFFFFFFu, s, off);
        if (lane == 0) g_partials[blockIdx.x] = s;
    }
}

__global__ __launch_bounds__(1024) void kan_final_kernel(float* __restrict__ out)
{
    // One block of 1024 threads reduces NBLOCKS partials.
    float acc = (threadIdx.x < NBLOCKS) ? g_partials[threadIdx.x] : 0.0f;

    #pragma unroll
    for (int off = 16; off > 0; off >>= 1)
        acc += __shfl_xor_sync(0xFFFFFFFFu, acc, off);

    __shared__ float warp_sums[32];
    int lane = threadIdx.x & 31;
    int wid = threadIdx.x >> 5;
    if (lane == 0) warp_sums[wid] = acc;
    __syncthreads();

    if (wid == 0) {
        float s = (lane < 32) ? warp_sums[lane] : 0.0f;
        #pragma unroll
        for (int off = 16; off > 0; off >>= 1)
            s += __shfl_xor_sync(0xFFFFFFFFu, s, off);
        if (lane == 0) out[0] = fmaxf(s, 0.0f);  // outer relu
    }
}

extern "C" void kernel_launch(void* const* d_in, const int* in_sizes, int n_in,
                              void* d_out, int out_size)
{
    const float* x = (const float*)d_in[0];
    float* out = (float*)d_out;
    int n = in_sizes[0];
    int n_vec4 = n / 4;  // N = 2^25, divisible by 4

    kan_partial_kernel<<<NBLOCKS, NTHREADS>>>(x, n_vec4);
    kan_final_kernel<<<1, 1024>>>(out);
}